// round 5
// baseline (speedup 1.0000x reference)
#include <cuda_runtime.h>
#include <math.h>

#define NMAX 20000
#define KNN 6
#define KCAND 7
#define NPART16 28
#define NPART32 14
#define NPARTMAX 28

typedef unsigned long long u64;

// ---------------- scratch (device globals; no allocation allowed) ----------------
__device__ __align__(16) float g_cnt [NMAX];
__device__ __align__(16) float g_agg1[NMAX*16];
__device__ __align__(16) float g_x1  [NMAX*16];
__device__ __align__(16) float g_sq1 [NMAX];
__device__ __align__(16) int   g_idx1[NMAX*KNN];
__device__ __align__(16) float g_y1  [NMAX*32];
__device__ __align__(16) float g_sq2 [NMAX];
__device__ __align__(16) float g_cat0[NMAX*48];
__device__ __align__(16) float g_agg2[NMAX*48];
__device__ __align__(16) int   g_idx2[NMAX*KNN];
__device__ __align__(16) float g_x3  [NMAX*64];
__device__ __align__(16) float g_y2  [NMAX*32];
__device__ __align__(16) float g_h1  [NMAX*96];
__device__ __align__(16) float g_cd  [NMAX*NPARTMAX*KCAND];
__device__ __align__(16) int   g_ci  [NMAX*NPARTMAX*KCAND];

// ---------------- packed f32x2 helpers ----------------
__device__ __forceinline__ u64 f2fma(u64 a, u64 b, u64 c){
    u64 d;
    asm("fma.rn.f32x2 %0, %1, %2, %3;" : "=l"(d) : "l"(a), "l"(b), "l"(c));
    return d;
}
__device__ __forceinline__ u64 f2mul(u64 a, u64 b){
    u64 d;
    asm("mul.rn.f32x2 %0, %1, %2;" : "=l"(d) : "l"(a), "l"(b));
    return d;
}
__device__ __forceinline__ float f2hadd(u64 a){
    float lo, hi;
    asm("mov.b64 {%0, %1}, %2;" : "=f"(lo), "=f"(hi) : "l"(a));
    return lo + hi;
}
__device__ __forceinline__ u64 fpack2(float lo, float hi){
    u64 d;
    asm("mov.b64 %0, {%1, %2};" : "=l"(d) : "f"(lo), "f"(hi));
    return d;
}

// ---------------- init: agg1 = x (self loop), cnt = 1 ----------------
__global__ void init1_kernel(const float* __restrict__ x, int n){
    int t = blockIdx.x*blockDim.x + threadIdx.x;
    if (t < n*16) g_agg1[t] = x[t];
    if (t < n)    g_cnt[t]  = 1.0f;
}

// ---------------- scatter-add of x[src] into agg1[dst], count edges ----------------
__global__ void scatter1_kernel(const int* __restrict__ src, const int* __restrict__ dst,
                                const float* __restrict__ x, int E){
    int t = blockIdx.x*blockDim.x + threadIdx.x;
    int e = t >> 2;
    if (e >= E) return;
    int q = t & 3;
    int s = src[e], d = dst[e];
    if (q == 0) atomicAdd(&g_cnt[d], 1.0f);
    float4 v = reinterpret_cast<const float4*>(x)[s*4 + q];
    float* a = &g_agg1[d*16 + q*4];
    atomicAdd(a+0, v.x); atomicAdd(a+1, v.y); atomicAdd(a+2, v.z); atomicAdd(a+3, v.w);
}

// ---------------- feast: out = relu((agg/cnt) @ W + b), optional ||row||^2 ----------------
template<int IN, int OUT, bool WSQ>
__global__ void feast_kernel(const float* __restrict__ agg, const float* __restrict__ W,
                             const float* __restrict__ b, int n,
                             float* __restrict__ out, float* __restrict__ sqout){
    __shared__ float sW[IN*OUT];
    __shared__ float sb[OUT];
    for (int t = threadIdx.x; t < IN*OUT; t += blockDim.x) sW[t] = W[t];
    for (int t = threadIdx.x; t < OUT;    t += blockDim.x) sb[t] = b[t];
    __syncthreads();
    int i = blockIdx.x*blockDim.x + threadIdx.x;
    if (i >= n) return;
    float inv = 1.0f / g_cnt[i];
    float acc[OUT];
#pragma unroll
    for (int c = 0; c < OUT; c++) acc[c] = sb[c];
    for (int d = 0; d < IN; d++){
        float v = agg[i*IN+d] * inv;
#pragma unroll
        for (int c = 0; c < OUT; c++) acc[c] = fmaf(v, sW[d*OUT+c], acc[c]);
    }
    float sq = 0.f;
#pragma unroll
    for (int c = 0; c < OUT; c++){
        float r = fmaxf(acc[c], 0.f);
        out[i*OUT+c] = r;
        sq = fmaf(r, r, sq);
    }
    if (WSQ) sqout[i] = sq;
}

// ---------------- streaming top-7 insertion (ascending-j scan) ----------------
__device__ __forceinline__ void upd7(float d, int j, float bd[KCAND], int bi[KCAND]){
    if (d < bd[KCAND-1]){
        bd[KCAND-1] = d; bi[KCAND-1] = j;
#pragma unroll
        for (int k = KCAND-1; k > 0; k--){
            if (bd[k] < bd[k-1]){
                float td = bd[k]; bd[k] = bd[k-1]; bd[k-1] = td;
                int   ti = bi[k]; bi[k] = bi[k-1]; bi[k-1] = ti;
            }
        }
    }
}

// ---------------- kNN, DIM=16, 2 queries/thread ----------------
// acc init = (sq_j, 0); queries pre-scaled by -2 => e = lo + hi directly.
// Self kept in list (strict minimum); merge kernel excludes it.
__global__ void __launch_bounds__(128)
knn2q16_kernel(const float* __restrict__ X, const float* __restrict__ sq,
               int n, int chunk, int half, int npart){
    const int TS = 128;
    const int Q = 4;                 // ulonglong2 (16B) per row of 64B
    __shared__ float4 xs[TS*Q];
    __shared__ float  sqs[TS];
    int tid = threadIdx.x;
    int i0 = blockIdx.x*128 + tid;
    int i1 = i0 + half;
    bool vA = (i0 < half);
    bool vB = vA && (i1 < n);
    int p = blockIdx.y;
    int jbeg = p * chunk;
    int jend = min(n, jbeg + chunk);

    const u64* Xp = (const u64*)X;
    int ia = vA ? i0 : 0;
    int ib = vB ? i1 : 0;
    u64 m2 = fpack2(-2.0f, -2.0f);
    u64 xa[8], xb[8];
#pragma unroll
    for (int d = 0; d < 8; d++){
        xa[d] = f2mul(Xp[(size_t)ia*8 + d], m2);
        xb[d] = f2mul(Xp[(size_t)ib*8 + d], m2);
    }
    float bdA[KCAND], bdB[KCAND]; int biA[KCAND], biB[KCAND];
#pragma unroll
    for (int k = 0; k < KCAND; k++){
        bdA[k] = INFINITY; biA[k] = -1;
        bdB[k] = INFINITY; biB[k] = -1;
    }

    for (int jt = jbeg; jt < jend; jt += TS){
        int tile = min(TS, jend - jt);
        __syncthreads();
        for (int t = tid; t < tile*Q; t += 128)
            xs[t] = reinterpret_cast<const float4*>(X)[jt*Q + t];
        for (int t = tid; t < TS; t += 128)
            sqs[t] = (t < tile) ? sq[jt + t] : INFINITY;
        __syncthreads();
        const ulonglong2* xp = (const ulonglong2*)xs;
        const float4* sq4 = (const float4*)sqs;

#pragma unroll 1
        for (int jj = 0; jj < TS; jj += 4){
            float4 sv = sq4[jj >> 2];
            u64 aA0 = (u64)__float_as_uint(sv.x);
            u64 aA1 = (u64)__float_as_uint(sv.y);
            u64 aA2 = (u64)__float_as_uint(sv.z);
            u64 aA3 = (u64)__float_as_uint(sv.w);
            u64 aB0 = aA0, aB1 = aA1, aB2 = aA2, aB3 = aA3;
            const ulonglong2* bp = xp + (jj << 2);
#pragma unroll
            for (int q = 0; q < Q; q++){
                ulonglong2 p0 = bp[q];
                ulonglong2 p1 = bp[4 + q];
                ulonglong2 p2 = bp[8 + q];
                ulonglong2 p3 = bp[12 + q];
                u64 w0 = xa[2*q], w1 = xa[2*q+1];
                aA0 = f2fma(w0, p0.x, aA0); aA0 = f2fma(w1, p0.y, aA0);
                aA1 = f2fma(w0, p1.x, aA1); aA1 = f2fma(w1, p1.y, aA1);
                aA2 = f2fma(w0, p2.x, aA2); aA2 = f2fma(w1, p2.y, aA2);
                aA3 = f2fma(w0, p3.x, aA3); aA3 = f2fma(w1, p3.y, aA3);
                u64 v0 = xb[2*q], v1 = xb[2*q+1];
                aB0 = f2fma(v0, p0.x, aB0); aB0 = f2fma(v1, p0.y, aB0);
                aB1 = f2fma(v0, p1.x, aB1); aB1 = f2fma(v1, p1.y, aB1);
                aB2 = f2fma(v0, p2.x, aB2); aB2 = f2fma(v1, p2.y, aB2);
                aB3 = f2fma(v0, p3.x, aB3); aB3 = f2fma(v1, p3.y, aB3);
            }
            int j0 = jt + jj;

            float eA0 = f2hadd(aA0);
            float eA1 = f2hadd(aA1);
            float eA2 = f2hadd(aA2);
            float eA3 = f2hadd(aA3);
            float mA = fminf(fminf(eA0, eA1), fminf(eA2, eA3));
            if (mA < bdA[KCAND-1]){
                upd7(eA0, j0+0, bdA, biA);
                upd7(eA1, j0+1, bdA, biA);
                upd7(eA2, j0+2, bdA, biA);
                upd7(eA3, j0+3, bdA, biA);
            }

            float eB0 = f2hadd(aB0);
            float eB1 = f2hadd(aB1);
            float eB2 = f2hadd(aB2);
            float eB3 = f2hadd(aB3);
            float mB = fminf(fminf(eB0, eB1), fminf(eB2, eB3));
            if (mB < bdB[KCAND-1]){
                upd7(eB0, j0+0, bdB, biB);
                upd7(eB1, j0+1, bdB, biB);
                upd7(eB2, j0+2, bdB, biB);
                upd7(eB3, j0+3, bdB, biB);
            }
        }
    }
    if (vA){
        int base = (i0*npart + p)*KCAND;
#pragma unroll
        for (int k = 0; k < KCAND; k++){ g_cd[base+k] = bdA[k]; g_ci[base+k] = biA[k]; }
    }
    if (vB){
        int base = (i1*npart + p)*KCAND;
#pragma unroll
        for (int k = 0; k < KCAND; k++){ g_cd[base+k] = bdB[k]; g_ci[base+k] = biB[k]; }
    }
}

// ---------------- kNN, DIM=32, 1 query/thread ----------------
__global__ void __launch_bounds__(128)
knn1q32_kernel(const float* __restrict__ X, const float* __restrict__ sq,
               int n, int chunk, int npart){
    const int TS = 128;
    const int Q = 8;                 // 8 x 16B per 128B row
    __shared__ float4 xs[TS*Q];
    __shared__ float  sqs[TS];
    int tid = threadIdx.x;
    int i = blockIdx.x*128 + tid;
    bool vA = (i < n);
    int p = blockIdx.y;
    int jbeg = p * chunk;
    int jend = min(n, jbeg + chunk);

    const u64* Xp = (const u64*)X;
    int ia = vA ? i : 0;
    u64 m2 = fpack2(-2.0f, -2.0f);
    u64 xa[16];
#pragma unroll
    for (int d = 0; d < 16; d++)
        xa[d] = f2mul(Xp[(size_t)ia*16 + d], m2);

    float bd[KCAND]; int bi[KCAND];
#pragma unroll
    for (int k = 0; k < KCAND; k++){ bd[k] = INFINITY; bi[k] = -1; }

    for (int jt = jbeg; jt < jend; jt += TS){
        int tile = min(TS, jend - jt);
        __syncthreads();
        for (int t = tid; t < tile*Q; t += 128)
            xs[t] = reinterpret_cast<const float4*>(X)[jt*Q + t];
        for (int t = tid; t < TS; t += 128)
            sqs[t] = (t < tile) ? sq[jt + t] : INFINITY;
        __syncthreads();
        const ulonglong2* xp = (const ulonglong2*)xs;
        const float4* sq4 = (const float4*)sqs;

#pragma unroll 1
        for (int jj = 0; jj < TS; jj += 4){
            float4 sv = sq4[jj >> 2];
            u64 a0 = (u64)__float_as_uint(sv.x);
            u64 a1 = (u64)__float_as_uint(sv.y);
            u64 a2 = (u64)__float_as_uint(sv.z);
            u64 a3 = (u64)__float_as_uint(sv.w);
            const ulonglong2* bp = xp + (jj << 3);
#pragma unroll
            for (int q = 0; q < Q; q++){
                ulonglong2 p0 = bp[q];
                ulonglong2 p1 = bp[8 + q];
                ulonglong2 p2 = bp[16 + q];
                ulonglong2 p3 = bp[24 + q];
                u64 w0 = xa[2*q], w1 = xa[2*q+1];
                a0 = f2fma(w0, p0.x, a0); a0 = f2fma(w1, p0.y, a0);
                a1 = f2fma(w0, p1.x, a1); a1 = f2fma(w1, p1.y, a1);
                a2 = f2fma(w0, p2.x, a2); a2 = f2fma(w1, p2.y, a2);
                a3 = f2fma(w0, p3.x, a3); a3 = f2fma(w1, p3.y, a3);
            }
            int j0 = jt + jj;
            float e0 = f2hadd(a0);
            float e1 = f2hadd(a1);
            float e2 = f2hadd(a2);
            float e3 = f2hadd(a3);
            float m = fminf(fminf(e0, e1), fminf(e2, e3));
            if (m < bd[KCAND-1]){
                upd7(e0, j0+0, bd, bi);
                upd7(e1, j0+1, bd, bi);
                upd7(e2, j0+2, bd, bi);
                upd7(e3, j0+3, bd, bi);
            }
        }
    }
    if (vA){
        int base = (i*npart + p)*KCAND;
#pragma unroll
        for (int k = 0; k < KCAND; k++){ g_cd[base+k] = bd[k]; g_ci[base+k] = bi[k]; }
    }
}

// ---------------- merge npart*7 candidates -> global top-6 per node ----------------
// Skips self (j==i) and empty (-1). Key = (distance, index) lexicographic.
__global__ void knn_merge_kernel(int n, int npart, int* __restrict__ outidx){
    int i = blockIdx.x*blockDim.x + threadIdx.x;
    if (i >= n) return;
    float bd[KNN]; unsigned bi[KNN];
#pragma unroll
    for (int k = 0; k < KNN; k++){ bd[k] = INFINITY; bi[k] = 0xFFFFFFFFu; }
    int base = i*npart*KCAND;
    int cnt = npart*KCAND;
    for (int c = 0; c < cnt; c++){
        float d = g_cd[base+c];
        int   jraw = g_ci[base+c];
        if (jraw < 0 || jraw == i) continue;
        unsigned j = (unsigned)jraw;
        if (d < bd[KNN-1] || (d == bd[KNN-1] && j < bi[KNN-1])){
            bd[KNN-1] = d; bi[KNN-1] = j;
#pragma unroll
            for (int k = KNN-1; k > 0; k--){
                bool sw = (bd[k] < bd[k-1]) || (bd[k] == bd[k-1] && bi[k] < bi[k-1]);
                if (sw){
                    float td = bd[k]; bd[k] = bd[k-1]; bd[k-1] = td;
                    unsigned ti = bi[k]; bi[k] = bi[k-1]; bi[k-1] = ti;
                }
            }
        }
    }
#pragma unroll
    for (int k = 0; k < KNN; k++) outidx[i*KNN+k] = (int)bi[k];
}

// ---------------- dynamic edge conv ----------------
template<int F>
__global__ void edgeconv_kernel(const float* __restrict__ X, const int* __restrict__ idx,
                                const float* __restrict__ W1, const float* __restrict__ b1,
                                const float* __restrict__ W2, const float* __restrict__ b2,
                                int n, float* __restrict__ Y, float* __restrict__ sqout){
    __shared__ float sW1[2*F*32];
    __shared__ float sb1[32];
    __shared__ float sW2[32*32];
    __shared__ float sb2[32];
    for (int t = threadIdx.x; t < 2*F*32; t += blockDim.x) sW1[t] = W1[t];
    for (int t = threadIdx.x; t < 32*32;  t += blockDim.x) sW2[t] = W2[t];
    if (threadIdx.x < 32){ sb1[threadIdx.x] = b1[threadIdx.x]; sb2[threadIdx.x] = b2[threadIdx.x]; }
    __syncthreads();
    int i = blockIdx.x*blockDim.x + threadIdx.x;
    if (i >= n) return;

    float base[32];
#pragma unroll
    for (int c = 0; c < 32; c++) base[c] = sb1[c];
    for (int d = 0; d < F; d++){
        float v = X[i*F+d];
#pragma unroll
        for (int c = 0; c < 32; c++) base[c] = fmaf(v, sW1[d*32+c], base[c]);
    }
    float acc[32];
#pragma unroll
    for (int c = 0; c < 32; c++) acc[c] = -INFINITY;

    for (int kk = 0; kk < KNN; kk++){
        int j = idx[i*KNN+kk];
        float h[32];
#pragma unroll
        for (int c = 0; c < 32; c++) h[c] = base[c];
        for (int d = 0; d < F; d++){
            float v = X[j*F+d] - X[i*F+d];
#pragma unroll
            for (int c = 0; c < 32; c++) h[c] = fmaf(v, sW1[(F+d)*32+c], h[c]);
        }
#pragma unroll
        for (int c = 0; c < 32; c++) h[c] = fmaxf(h[c], 0.f);
#pragma unroll
        for (int c = 0; c < 32; c++){
            float o = sb2[c];
#pragma unroll
            for (int k = 0; k < 32; k++) o = fmaf(h[k], sW2[k*32+c], o);
            acc[c] = fmaxf(acc[c], o);
        }
    }
    float sqv = 0.f;
#pragma unroll
    for (int c = 0; c < 32; c++){
        float r = fmaxf(acc[c], 0.f);
        Y[i*32+c] = r;
        sqv = fmaf(r, r, sqv);
    }
    if (sqout) sqout[i] = sqv;
}

// ---------------- cat0 = [x1 | y1]; agg2 init = cat0 (self loop) ----------------
__global__ void cat0_kernel(int n){
    int t = blockIdx.x*blockDim.x + threadIdx.x;
    if (t >= n*48) return;
    int i = t / 48, d = t % 48;
    float v = (d < 16) ? g_x1[i*16+d] : g_y1[i*32 + (d-16)];
    g_cat0[t] = v;
    g_agg2[t] = v;
}

__global__ void scatter2_kernel(const int* __restrict__ src, const int* __restrict__ dst, int E){
    int t = blockIdx.x*blockDim.x + threadIdx.x;
    int e = t / 12;
    if (e >= E) return;
    int q = t % 12;
    int s = src[e], d = dst[e];
    float4 v = reinterpret_cast<const float4*>(g_cat0)[s*12 + q];
    float* a = &g_agg2[d*48 + q*4];
    atomicAdd(a+0, v.x); atomicAdd(a+1, v.y); atomicAdd(a+2, v.z); atomicAdd(a+3, v.w);
}

// ---------------- MLP layer 1 ----------------
__global__ void mlp1_kernel(const float* __restrict__ W, const float* __restrict__ b, int n){
    __shared__ float sW[96*96];
    __shared__ float sb[96];
    for (int t = threadIdx.x; t < 96*96; t += blockDim.x) sW[t] = W[t];
    for (int t = threadIdx.x; t < 96;    t += blockDim.x) sb[t] = b[t];
    __syncthreads();
    int i = blockIdx.x*blockDim.x + threadIdx.x;
    if (i >= n) return;
    float acc[96];
#pragma unroll
    for (int c = 0; c < 96; c++) acc[c] = sb[c];
    for (int d = 0; d < 64; d++){
        float v = g_x3[i*64+d];
#pragma unroll
        for (int c = 0; c < 96; c++) acc[c] = fmaf(v, sW[d*96+c], acc[c]);
    }
    for (int d = 0; d < 32; d++){
        float v = g_y2[i*32+d];
#pragma unroll
        for (int c = 0; c < 96; c++) acc[c] = fmaf(v, sW[(64+d)*96+c], acc[c]);
    }
#pragma unroll
    for (int c = 0; c < 96; c++) g_h1[i*96+c] = fmaxf(acc[c], 0.f);
}

// ---------------- MLP layers 2..out ----------------
__global__ void mlp2_kernel(const float* __restrict__ W2, const float* __restrict__ b2,
                            const float* __restrict__ W3, const float* __restrict__ b3,
                            const float* __restrict__ Wo, const float* __restrict__ bo,
                            int n, float* __restrict__ out){
    __shared__ float sW2[96*32]; __shared__ float sb2v[32];
    __shared__ float sW3[32*8];  __shared__ float sb3v[8];
    __shared__ float sWo[8];     __shared__ float sbo;
    for (int t = threadIdx.x; t < 96*32; t += blockDim.x) sW2[t] = W2[t];
    for (int t = threadIdx.x; t < 32*8;  t += blockDim.x) sW3[t] = W3[t];
    if (threadIdx.x < 32) sb2v[threadIdx.x] = b2[threadIdx.x];
    if (threadIdx.x < 8){ sb3v[threadIdx.x] = b3[threadIdx.x]; sWo[threadIdx.x] = Wo[threadIdx.x]; }
    if (threadIdx.x == 0) sbo = bo[0];
    __syncthreads();
    int i = blockIdx.x*blockDim.x + threadIdx.x;
    if (i >= n) return;
    float h[32];
#pragma unroll
    for (int c = 0; c < 32; c++) h[c] = sb2v[c];
    for (int d = 0; d < 96; d++){
        float v = g_h1[i*96+d];
#pragma unroll
        for (int c = 0; c < 32; c++) h[c] = fmaf(v, sW2[d*32+c], h[c]);
    }
#pragma unroll
    for (int c = 0; c < 32; c++) h[c] = fmaxf(h[c], 0.f);
    float g[8];
#pragma unroll
    for (int c = 0; c < 8; c++){
        float o = sb3v[c];
#pragma unroll
        for (int k = 0; k < 32; k++) o = fmaf(h[k], sW3[k*8+c], o);
        g[c] = fmaxf(o, 0.f);
    }
    float z = sbo;
#pragma unroll
    for (int c = 0; c < 8; c++) z = fmaf(g[c], sWo[c], z);
    out[i] = 1.0f / (1.0f + expf(-z));
}

// ---------------- launch ----------------
extern "C" void kernel_launch(void* const* d_in, const int* in_sizes, int n_in,
                              void* d_out, int out_size){
    const float* x   = (const float*)d_in[0];
    const int*   ei  = (const int*)  d_in[1];
    int n = in_sizes[0] / 16;
    int E = in_sizes[1] / 2;
    const int* src = ei;
    const int* dst = ei + E;

    const float* cW1 = (const float*)d_in[2];
    const float* cb1 = (const float*)d_in[5];
    const float* cW3 = (const float*)d_in[6];
    const float* cb3 = (const float*)d_in[9];
    const float* e1W1=(const float*)d_in[10]; const float* e1b1=(const float*)d_in[11];
    const float* e1W2=(const float*)d_in[12]; const float* e1b2=(const float*)d_in[13];
    const float* e2W1=(const float*)d_in[14]; const float* e2b1=(const float*)d_in[15];
    const float* e2W2=(const float*)d_in[16]; const float* e2b2=(const float*)d_in[17];
    const float* l1W =(const float*)d_in[18]; const float* l1b =(const float*)d_in[19];
    const float* l2W =(const float*)d_in[20]; const float* l2b =(const float*)d_in[21];
    const float* l3W =(const float*)d_in[22]; const float* l3b =(const float*)d_in[23];
    const float* oW  =(const float*)d_in[24]; const float* ob  =(const float*)d_in[25];
    float* out = (float*)d_out;

    void *p_agg1, *p_x1, *p_sq1, *p_idx1, *p_y1, *p_sq2, *p_agg2, *p_idx2, *p_x3, *p_y2;
    cudaGetSymbolAddress(&p_agg1, g_agg1);
    cudaGetSymbolAddress(&p_x1,   g_x1);
    cudaGetSymbolAddress(&p_sq1,  g_sq1);
    cudaGetSymbolAddress(&p_idx1, g_idx1);
    cudaGetSymbolAddress(&p_y1,   g_y1);
    cudaGetSymbolAddress(&p_sq2,  g_sq2);
    cudaGetSymbolAddress(&p_agg2, g_agg2);
    cudaGetSymbolAddress(&p_idx2, g_idx2);
    cudaGetSymbolAddress(&p_x3,   g_x3);
    cudaGetSymbolAddress(&p_y2,   g_y2);

    int nb = (n + 127) / 128;
    int half = (n + 1) / 2;
    int nbq = (half + 127) / 128;
    int chunk16 = (n + NPART16 - 1) / NPART16;
    int chunk32 = (n + NPART32 - 1) / NPART32;
    dim3 grid16(nbq, NPART16);
    dim3 grid32(nb,  NPART32);

    // FeaSt 1 (heads=1 => attention == 1 => segment-mean then GEMM)
    init1_kernel<<<(n*16 + 255)/256, 256>>>(x, n);
    scatter1_kernel<<<(E*4 + 255)/256, 256>>>(src, dst, x, E);
    feast_kernel<16,16,true><<<nb,128>>>((const float*)p_agg1, cW1, cb1, n,
                                         (float*)p_x1, (float*)p_sq1);
    // kNN on x1 (dim 16): partitioned + merge
    knn2q16_kernel<<<grid16,128>>>((const float*)p_x1, (const float*)p_sq1, n, chunk16, half, NPART16);
    knn_merge_kernel<<<(n+255)/256,256>>>(n, NPART16, (int*)p_idx1);
    edgeconv_kernel<16><<<nb,128>>>((const float*)p_x1, (const int*)p_idx1,
                                    e1W1, e1b1, e1W2, e1b2, n,
                                    (float*)p_y1, (float*)p_sq2);
    // FeaSt 2 on cat0 = [x1|y1]
    cat0_kernel<<<(n*48 + 255)/256, 256>>>(n);
    scatter2_kernel<<<(E*12 + 255)/256, 256>>>(src, dst, E);
    feast_kernel<48,64,false><<<nb,128>>>((const float*)p_agg2, cW3, cb3, n,
                                          (float*)p_x3, nullptr);
    // kNN on y1 (dim 32): partitioned + merge
    knn1q32_kernel<<<grid32,128>>>((const float*)p_y1, (const float*)p_sq2, n, chunk32, NPART32);
    knn_merge_kernel<<<(n+255)/256,256>>>(n, NPART32, (int*)p_idx2);
    edgeconv_kernel<32><<<nb,128>>>((const float*)p_y1, (const int*)p_idx2,
                                    e2W1, e2b1, e2W2, e2b2, n,
                                    (float*)p_y2, nullptr);
    // Final MLP
    mlp1_kernel<<<nb,128>>>(l1W, l1b, n);
    mlp2_kernel<<<nb,128>>>(l2W, l2b, l3W, l3b, oW, ob, n, out);
}

// round 6
// speedup vs baseline: 1.0387x; 1.0387x over previous
#include <cuda_runtime.h>
#include <math.h>

#define NMAX 20000
#define KNN 6
#define KCAND 7
#define NPARTK 6
#define NSUB 4

typedef unsigned int u32;

// ---------------- scratch (device globals; no allocation allowed) ----------------
__device__ __align__(16) float g_cnt [NMAX];
__device__ __align__(16) float g_agg1[NMAX*16];
__device__ __align__(16) float g_x1  [NMAX*16];
__device__ __align__(16) float g_sq1 [NMAX];
__device__ __align__(16) int   g_idx1[NMAX*KNN];
__device__ __align__(16) float g_y1  [NMAX*32];
__device__ __align__(16) float g_sq2 [NMAX];
__device__ __align__(16) float g_cat0[NMAX*48];
__device__ __align__(16) float g_agg2[NMAX*48];
__device__ __align__(16) int   g_idx2[NMAX*KNN];
__device__ __align__(16) float g_x3  [NMAX*64];
__device__ __align__(16) float g_y2  [NMAX*32];
__device__ __align__(16) float g_h1  [NMAX*96];
__device__ __align__(16) float g_x1h [NMAX*16];
__device__ __align__(16) float g_x1l [NMAX*16];
__device__ __align__(16) float g_y1h [NMAX*32];
__device__ __align__(16) float g_y1l [NMAX*32];
__device__ __align__(16) float g_cd  [NMAX*NPARTK*NSUB*KCAND];
__device__ __align__(16) int   g_ci  [NMAX*NPARTK*NSUB*KCAND];

// ---------------- tf32 helpers ----------------
__device__ __forceinline__ float tf32r(float x){
    float r; asm("cvt.rna.tf32.f32 %0, %1;" : "=f"(r) : "f"(x)); return r;
}

#define MMA_TF32(c0,c1,c2,c3,a0,a1,a2,a3,b0,b1) \
    asm volatile("mma.sync.aligned.m16n8k8.row.col.f32.tf32.tf32.f32 " \
        "{%0,%1,%2,%3}, {%4,%5,%6,%7}, {%8,%9}, {%0,%1,%2,%3};" \
        : "+f"(c0), "+f"(c1), "+f"(c2), "+f"(c3) \
        : "r"(a0), "r"(a1), "r"(a2), "r"(a3), "r"(b0), "r"(b1))

// ---------------- init: agg1 = x (self loop), cnt = 1 ----------------
__global__ void init1_kernel(const float* __restrict__ x, int n){
    int t = blockIdx.x*blockDim.x + threadIdx.x;
    if (t < n*16) g_agg1[t] = x[t];
    if (t < n)    g_cnt[t]  = 1.0f;
}

// ---------------- scatter-add of x[src] into agg1[dst], count edges ----------------
__global__ void scatter1_kernel(const int* __restrict__ src, const int* __restrict__ dst,
                                const float* __restrict__ x, int E){
    int t = blockIdx.x*blockDim.x + threadIdx.x;
    int e = t >> 2;
    if (e >= E) return;
    int q = t & 3;
    int s = src[e], d = dst[e];
    if (q == 0) atomicAdd(&g_cnt[d], 1.0f);
    float4 v = reinterpret_cast<const float4*>(x)[s*4 + q];
    float* a = &g_agg1[d*16 + q*4];
    atomicAdd(a+0, v.x); atomicAdd(a+1, v.y); atomicAdd(a+2, v.z); atomicAdd(a+3, v.w);
}

// ---------------- feast: out = relu((agg/cnt) @ W + b), optional ||row||^2 ----------------
template<int IN, int OUT, bool WSQ>
__global__ void feast_kernel(const float* __restrict__ agg, const float* __restrict__ W,
                             const float* __restrict__ b, int n,
                             float* __restrict__ out, float* __restrict__ sqout){
    __shared__ float sW[IN*OUT];
    __shared__ float sb[OUT];
    for (int t = threadIdx.x; t < IN*OUT; t += blockDim.x) sW[t] = W[t];
    for (int t = threadIdx.x; t < OUT;    t += blockDim.x) sb[t] = b[t];
    __syncthreads();
    int i = blockIdx.x*blockDim.x + threadIdx.x;
    if (i >= n) return;
    float inv = 1.0f / g_cnt[i];
    float acc[OUT];
#pragma unroll
    for (int c = 0; c < OUT; c++) acc[c] = sb[c];
    for (int d = 0; d < IN; d++){
        float v = agg[i*IN+d] * inv;
#pragma unroll
        for (int c = 0; c < OUT; c++) acc[c] = fmaf(v, sW[d*OUT+c], acc[c]);
    }
    float sq = 0.f;
#pragma unroll
    for (int c = 0; c < OUT; c++){
        float r = fmaxf(acc[c], 0.f);
        out[i*OUT+c] = r;
        sq = fmaf(r, r, sq);
    }
    if (WSQ) sqout[i] = sq;
}

// ---------------- split x into tf32 hi/lo ----------------
__global__ void split_kernel(const float* __restrict__ X, int total,
                             float* __restrict__ Xh, float* __restrict__ Xl){
    int t = blockIdx.x*blockDim.x + threadIdx.x;
    if (t >= total) return;
    float v = X[t];
    float h = tf32r(v);
    Xh[t] = h;
    Xl[t] = tf32r(v - h);
}

// ---------------- streaming top-7 insertion ----------------
__device__ __forceinline__ void upd7(float d, int j, float bd[KCAND], int bi[KCAND]){
    if (d < bd[KCAND-1]){
        bd[KCAND-1] = d; bi[KCAND-1] = j;
#pragma unroll
        for (int k = KCAND-1; k > 0; k--){
            if (bd[k] < bd[k-1]){
                float td = bd[k]; bd[k] = bd[k-1]; bd[k-1] = td;
                int   ti = bi[k]; bi[k] = bi[k-1]; bi[k-1] = ti;
            }
        }
    }
}

// ---------------- tensor-core kNN ----------------
// d(i,j) = sq_j - 2 x_i.x_j via split-tf32 mma.m16n8k8 (3 compensated passes).
// A = (-2x) split (power-of-2 scale is tf32-exact), C initialized to sq_j,
// so the mma accumulator IS the distance. Each warp owns 16 query rows;
// 8 warps/block share staged j tiles. Thread keeps 7-deep lists for its
// 2 rows over its j-residue class (col group g = lane&3), dumped for merge.
template<int DIM, int PAD>
__global__ void __launch_bounds__(256)
knn_mma_kernel(const float* __restrict__ Xh, const float* __restrict__ Xl,
               const float* __restrict__ sq, int n, int chunk, int npart){
    const int KC = DIM/8;
    const int Q4 = DIM/4;
    __shared__ float bh[128*PAD];
    __shared__ float bl[128*PAD];
    __shared__ float sqs[128];

    int tid = threadIdx.x;
    int w = tid >> 5;
    int lane = tid & 31;
    int g = lane & 3;
    int rsub = lane >> 2;          // 0..7
    int qbase = blockIdx.x*128 + w*16;
    int r0 = qbase + rsub;
    int r1 = r0 + 8;
    int p = blockIdx.y;
    int jbeg = p * chunk;
    int jend = min(n, jbeg + chunk);

    // A fragments: rows r0/r1, k-cols g and g+4 per 8-wide k chunk; hi & lo, scaled by -2.
    int rr0 = min(r0, n-1), rr1 = min(r1, n-1);
    u32 ah[KC][4], al[KC][4];
#pragma unroll
    for (int kc = 0; kc < KC; kc++){
        ah[kc][0] = __float_as_uint(-2.0f * Xh[rr0*DIM + kc*8 + g]);
        ah[kc][1] = __float_as_uint(-2.0f * Xh[rr1*DIM + kc*8 + g]);
        ah[kc][2] = __float_as_uint(-2.0f * Xh[rr0*DIM + kc*8 + g + 4]);
        ah[kc][3] = __float_as_uint(-2.0f * Xh[rr1*DIM + kc*8 + g + 4]);
        al[kc][0] = __float_as_uint(-2.0f * Xl[rr0*DIM + kc*8 + g]);
        al[kc][1] = __float_as_uint(-2.0f * Xl[rr1*DIM + kc*8 + g]);
        al[kc][2] = __float_as_uint(-2.0f * Xl[rr0*DIM + kc*8 + g + 4]);
        al[kc][3] = __float_as_uint(-2.0f * Xl[rr1*DIM + kc*8 + g + 4]);
    }

    float bdA[KCAND], bdB[KCAND]; int biA[KCAND], biB[KCAND];
#pragma unroll
    for (int k = 0; k < KCAND; k++){
        bdA[k] = INFINITY; biA[k] = -1;
        bdB[k] = INFINITY; biB[k] = -1;
    }

    for (int jt = jbeg; jt < jend; jt += 128){
        __syncthreads();
        // stage 128 j rows of hi/lo into padded smem
        for (int idx = tid; idx < 128*Q4; idx += 256){
            int jr = idx / Q4;
            int q4 = idx % Q4;
            int gj = jt + jr;
            float4 vh = {0.f,0.f,0.f,0.f}, vl = {0.f,0.f,0.f,0.f};
            if (gj < jend){
                vh = reinterpret_cast<const float4*>(Xh)[gj*Q4 + q4];
                vl = reinterpret_cast<const float4*>(Xl)[gj*Q4 + q4];
            }
            int sb = jr*PAD + q4*4;
            bh[sb+0]=vh.x; bh[sb+1]=vh.y; bh[sb+2]=vh.z; bh[sb+3]=vh.w;
            bl[sb+0]=vl.x; bl[sb+1]=vl.y; bl[sb+2]=vl.z; bl[sb+3]=vl.w;
        }
        for (int idx = tid; idx < 128; idx += 256)
            sqs[idx] = (jt + idx < jend) ? sq[jt + idx] : INFINITY;
        __syncthreads();

#pragma unroll 2
        for (int js = 0; js < 128; js += 8){
            float2 s2 = *reinterpret_cast<const float2*>(&sqs[js + 2*g]);
            float c0 = s2.x, c1 = s2.y, c2 = s2.x, c3 = s2.y;
            int rb = (js + rsub)*PAD + g;
#pragma unroll
            for (int kc = 0; kc < KC; kc++){
                u32 b0h = __float_as_uint(bh[rb + kc*8]);
                u32 b1h = __float_as_uint(bh[rb + kc*8 + 4]);
                u32 b0l = __float_as_uint(bl[rb + kc*8]);
                u32 b1l = __float_as_uint(bl[rb + kc*8 + 4]);
                MMA_TF32(c0,c1,c2,c3, ah[kc][0],ah[kc][1],ah[kc][2],ah[kc][3], b0h,b1h);
                MMA_TF32(c0,c1,c2,c3, al[kc][0],al[kc][1],al[kc][2],al[kc][3], b0h,b1h);
                MMA_TF32(c0,c1,c2,c3, ah[kc][0],ah[kc][1],ah[kc][2],ah[kc][3], b0l,b1l);
            }
            int j0 = jt + js + 2*g;
            upd7(c0, j0,   bdA, biA);
            upd7(c1, j0+1, bdA, biA);
            upd7(c2, j0,   bdB, biB);
            upd7(c3, j0+1, bdB, biB);
        }
    }
    if (r0 < n){
        int base = ((r0*npart + p)*NSUB + g)*KCAND;
#pragma unroll
        for (int k = 0; k < KCAND; k++){ g_cd[base+k] = bdA[k]; g_ci[base+k] = biA[k]; }
    }
    if (r1 < n){
        int base = ((r1*npart + p)*NSUB + g)*KCAND;
#pragma unroll
        for (int k = 0; k < KCAND; k++){ g_cd[base+k] = bdB[k]; g_ci[base+k] = biB[k]; }
    }
}

// ---------------- merge candidates -> global top-6 per node ----------------
// Skips self (j==i) and empties. Key = (distance, index) lexicographic.
__global__ void knn_merge_kernel(int n, int npart, int* __restrict__ outidx){
    int i = blockIdx.x*blockDim.x + threadIdx.x;
    if (i >= n) return;
    float bd[KNN]; unsigned bi[KNN];
#pragma unroll
    for (int k = 0; k < KNN; k++){ bd[k] = INFINITY; bi[k] = 0xFFFFFFFFu; }
    int base = i*npart*NSUB*KCAND;
    int cnt = npart*NSUB*KCAND;
    for (int c = 0; c < cnt; c++){
        float d = g_cd[base+c];
        int jraw = g_ci[base+c];
        if (jraw < 0 || jraw == i) continue;
        unsigned j = (unsigned)jraw;
        if (d < bd[KNN-1] || (d == bd[KNN-1] && j < bi[KNN-1])){
            bd[KNN-1] = d; bi[KNN-1] = j;
#pragma unroll
            for (int k = KNN-1; k > 0; k--){
                bool sw = (bd[k] < bd[k-1]) || (bd[k] == bd[k-1] && bi[k] < bi[k-1]);
                if (sw){
                    float td = bd[k]; bd[k] = bd[k-1]; bd[k-1] = td;
                    unsigned ti = bi[k]; bi[k] = bi[k-1]; bi[k-1] = ti;
                }
            }
        }
    }
#pragma unroll
    for (int k = 0; k < KNN; k++) outidx[i*KNN+k] = (int)bi[k];
}

// ---------------- dynamic edge conv ----------------
template<int F>
__global__ void edgeconv_kernel(const float* __restrict__ X, const int* __restrict__ idx,
                                const float* __restrict__ W1, const float* __restrict__ b1,
                                const float* __restrict__ W2, const float* __restrict__ b2,
                                int n, float* __restrict__ Y, float* __restrict__ sqout){
    __shared__ float sW1[2*F*32];
    __shared__ float sb1[32];
    __shared__ float sW2[32*32];
    __shared__ float sb2[32];
    for (int t = threadIdx.x; t < 2*F*32; t += blockDim.x) sW1[t] = W1[t];
    for (int t = threadIdx.x; t < 32*32;  t += blockDim.x) sW2[t] = W2[t];
    if (threadIdx.x < 32){ sb1[threadIdx.x] = b1[threadIdx.x]; sb2[threadIdx.x] = b2[threadIdx.x]; }
    __syncthreads();
    int i = blockIdx.x*blockDim.x + threadIdx.x;
    if (i >= n) return;

    float base[32];
#pragma unroll
    for (int c = 0; c < 32; c++) base[c] = sb1[c];
    for (int d = 0; d < F; d++){
        float v = X[i*F+d];
#pragma unroll
        for (int c = 0; c < 32; c++) base[c] = fmaf(v, sW1[d*32+c], base[c]);
    }
    float acc[32];
#pragma unroll
    for (int c = 0; c < 32; c++) acc[c] = -INFINITY;

    for (int kk = 0; kk < KNN; kk++){
        int j = idx[i*KNN+kk];
        float h[32];
#pragma unroll
        for (int c = 0; c < 32; c++) h[c] = base[c];
        for (int d = 0; d < F; d++){
            float v = X[j*F+d] - X[i*F+d];
#pragma unroll
            for (int c = 0; c < 32; c++) h[c] = fmaf(v, sW1[(F+d)*32+c], h[c]);
        }
#pragma unroll
        for (int c = 0; c < 32; c++) h[c] = fmaxf(h[c], 0.f);
#pragma unroll
        for (int c = 0; c < 32; c++){
            float o = sb2[c];
#pragma unroll
            for (int k = 0; k < 32; k++) o = fmaf(h[k], sW2[k*32+c], o);
            acc[c] = fmaxf(acc[c], o);
        }
    }
    float sqv = 0.f;
#pragma unroll
    for (int c = 0; c < 32; c++){
        float r = fmaxf(acc[c], 0.f);
        Y[i*32+c] = r;
        sqv = fmaf(r, r, sqv);
    }
    if (sqout) sqout[i] = sqv;
}

// ---------------- cat0 = [x1 | y1]; agg2 init = cat0 (self loop) ----------------
__global__ void cat0_kernel(int n){
    int t = blockIdx.x*blockDim.x + threadIdx.x;
    if (t >= n*48) return;
    int i = t / 48, d = t % 48;
    float v = (d < 16) ? g_x1[i*16+d] : g_y1[i*32 + (d-16)];
    g_cat0[t] = v;
    g_agg2[t] = v;
}

__global__ void scatter2_kernel(const int* __restrict__ src, const int* __restrict__ dst, int E){
    int t = blockIdx.x*blockDim.x + threadIdx.x;
    int e = t / 12;
    if (e >= E) return;
    int q = t % 12;
    int s = src[e], d = dst[e];
    float4 v = reinterpret_cast<const float4*>(g_cat0)[s*12 + q];
    float* a = &g_agg2[d*48 + q*4];
    atomicAdd(a+0, v.x); atomicAdd(a+1, v.y); atomicAdd(a+2, v.z); atomicAdd(a+3, v.w);
}

// ---------------- MLP layer 1 ----------------
__global__ void mlp1_kernel(const float* __restrict__ W, const float* __restrict__ b, int n){
    __shared__ float sW[96*96];
    __shared__ float sb[96];
    for (int t = threadIdx.x; t < 96*96; t += blockDim.x) sW[t] = W[t];
    for (int t = threadIdx.x; t < 96;    t += blockDim.x) sb[t] = b[t];
    __syncthreads();
    int i = blockIdx.x*blockDim.x + threadIdx.x;
    if (i >= n) return;
    float acc[96];
#pragma unroll
    for (int c = 0; c < 96; c++) acc[c] = sb[c];
    for (int d = 0; d < 64; d++){
        float v = g_x3[i*64+d];
#pragma unroll
        for (int c = 0; c < 96; c++) acc[c] = fmaf(v, sW[d*96+c], acc[c]);
    }
    for (int d = 0; d < 32; d++){
        float v = g_y2[i*32+d];
#pragma unroll
        for (int c = 0; c < 96; c++) acc[c] = fmaf(v, sW[(64+d)*96+c], acc[c]);
    }
#pragma unroll
    for (int c = 0; c < 96; c++) g_h1[i*96+c] = fmaxf(acc[c], 0.f);
}

// ---------------- MLP layers 2..out ----------------
__global__ void mlp2_kernel(const float* __restrict__ W2, const float* __restrict__ b2,
                            const float* __restrict__ W3, const float* __restrict__ b3,
                            const float* __restrict__ Wo, const float* __restrict__ bo,
                            int n, float* __restrict__ out){
    __shared__ float sW2[96*32]; __shared__ float sb2v[32];
    __shared__ float sW3[32*8];  __shared__ float sb3v[8];
    __shared__ float sWo[8];     __shared__ float sbo;
    for (int t = threadIdx.x; t < 96*32; t += blockDim.x) sW2[t] = W2[t];
    for (int t = threadIdx.x; t < 32*8;  t += blockDim.x) sW3[t] = W3[t];
    if (threadIdx.x < 32) sb2v[threadIdx.x] = b2[threadIdx.x];
    if (threadIdx.x < 8){ sb3v[threadIdx.x] = b3[threadIdx.x]; sWo[threadIdx.x] = Wo[threadIdx.x]; }
    if (threadIdx.x == 0) sbo = bo[0];
    __syncthreads();
    int i = blockIdx.x*blockDim.x + threadIdx.x;
    if (i >= n) return;
    float h[32];
#pragma unroll
    for (int c = 0; c < 32; c++) h[c] = sb2v[c];
    for (int d = 0; d < 96; d++){
        float v = g_h1[i*96+d];
#pragma unroll
        for (int c = 0; c < 32; c++) h[c] = fmaf(v, sW2[d*32+c], h[c]);
    }
#pragma unroll
    for (int c = 0; c < 32; c++) h[c] = fmaxf(h[c], 0.f);
    float g[8];
#pragma unroll
    for (int c = 0; c < 8; c++){
        float o = sb3v[c];
#pragma unroll
        for (int k = 0; k < 32; k++) o = fmaf(h[k], sW3[k*8+c], o);
        g[c] = fmaxf(o, 0.f);
    }
    float z = sbo;
#pragma unroll
    for (int c = 0; c < 8; c++) z = fmaf(g[c], sWo[c], z);
    out[i] = 1.0f / (1.0f + expf(-z));
}

// ---------------- launch ----------------
extern "C" void kernel_launch(void* const* d_in, const int* in_sizes, int n_in,
                              void* d_out, int out_size){
    const float* x   = (const float*)d_in[0];
    const int*   ei  = (const int*)  d_in[1];
    int n = in_sizes[0] / 16;
    int E = in_sizes[1] / 2;
    const int* src = ei;
    const int* dst = ei + E;

    const float* cW1 = (const float*)d_in[2];
    const float* cb1 = (const float*)d_in[5];
    const float* cW3 = (const float*)d_in[6];
    const float* cb3 = (const float*)d_in[9];
    const float* e1W1=(const float*)d_in[10]; const float* e1b1=(const float*)d_in[11];
    const float* e1W2=(const float*)d_in[12]; const float* e1b2=(const float*)d_in[13];
    const float* e2W1=(const float*)d_in[14]; const float* e2b1=(const float*)d_in[15];
    const float* e2W2=(const float*)d_in[16]; const float* e2b2=(const float*)d_in[17];
    const float* l1W =(const float*)d_in[18]; const float* l1b =(const float*)d_in[19];
    const float* l2W =(const float*)d_in[20]; const float* l2b =(const float*)d_in[21];
    const float* l3W =(const float*)d_in[22]; const float* l3b =(const float*)d_in[23];
    const float* oW  =(const float*)d_in[24]; const float* ob  =(const float*)d_in[25];
    float* out = (float*)d_out;

    void *p_agg1, *p_x1, *p_sq1, *p_idx1, *p_y1, *p_sq2, *p_agg2, *p_idx2, *p_x3, *p_y2;
    void *p_x1h, *p_x1l, *p_y1h, *p_y1l;
    cudaGetSymbolAddress(&p_agg1, g_agg1);
    cudaGetSymbolAddress(&p_x1,   g_x1);
    cudaGetSymbolAddress(&p_sq1,  g_sq1);
    cudaGetSymbolAddress(&p_idx1, g_idx1);
    cudaGetSymbolAddress(&p_y1,   g_y1);
    cudaGetSymbolAddress(&p_sq2,  g_sq2);
    cudaGetSymbolAddress(&p_agg2, g_agg2);
    cudaGetSymbolAddress(&p_idx2, g_idx2);
    cudaGetSymbolAddress(&p_x3,   g_x3);
    cudaGetSymbolAddress(&p_y2,   g_y2);
    cudaGetSymbolAddress(&p_x1h,  g_x1h);
    cudaGetSymbolAddress(&p_x1l,  g_x1l);
    cudaGetSymbolAddress(&p_y1h,  g_y1h);
    cudaGetSymbolAddress(&p_y1l,  g_y1l);

    int nb = (n + 127) / 128;
    int chunk = (n + NPARTK - 1) / NPARTK;
    dim3 knngrid(nb, NPARTK);

    // FeaSt 1 (heads=1 => attention == 1 => segment-mean then GEMM)
    init1_kernel<<<(n*16 + 255)/256, 256>>>(x, n);
    scatter1_kernel<<<(E*4 + 255)/256, 256>>>(src, dst, x, E);
    feast_kernel<16,16,true><<<nb,128>>>((const float*)p_agg1, cW1, cb1, n,
                                         (float*)p_x1, (float*)p_sq1);
    // kNN on x1 (dim 16): split-tf32 tensor-core distances + merge
    split_kernel<<<(n*16 + 255)/256, 256>>>((const float*)p_x1, n*16,
                                            (float*)p_x1h, (float*)p_x1l);
    knn_mma_kernel<16,20><<<knngrid,256>>>((const float*)p_x1h, (const float*)p_x1l,
                                           (const float*)p_sq1, n, chunk, NPARTK);
    knn_merge_kernel<<<(n+255)/256,256>>>(n, NPARTK, (int*)p_idx1);
    edgeconv_kernel<16><<<nb,128>>>((const float*)p_x1, (const int*)p_idx1,
                                    e1W1, e1b1, e1W2, e1b2, n,
                                    (float*)p_y1, (float*)p_sq2);
    // FeaSt 2 on cat0 = [x1|y1]
    cat0_kernel<<<(n*48 + 255)/256, 256>>>(n);
    scatter2_kernel<<<(E*12 + 255)/256, 256>>>(src, dst, E);
    feast_kernel<48,64,false><<<nb,128>>>((const float*)p_agg2, cW3, cb3, n,
                                          (float*)p_x3, nullptr);
    // kNN on y1 (dim 32): split-tf32 tensor-core distances + merge
    split_kernel<<<(n*32 + 255)/256, 256>>>((const float*)p_y1, n*32,
                                            (float*)p_y1h, (float*)p_y1l);
    knn_mma_kernel<32,36><<<knngrid,256>>>((const float*)p_y1h, (const float*)p_y1l,
                                           (const float*)p_sq2, n, chunk, NPARTK);
    knn_merge_kernel<<<(n+255)/256,256>>>(n, NPARTK, (int*)p_idx2);
    edgeconv_kernel<32><<<nb,128>>>((const float*)p_y1, (const int*)p_idx2,
                                    e2W1, e2b1, e2W2, e2b2, n,
                                    (float*)p_y2, nullptr);
    // Final MLP
    mlp1_kernel<<<nb,128>>>(l1W, l1b, n);
    mlp2_kernel<<<nb,128>>>(l2W, l2b, l3W, l3b, oW, ob, n, out);
}

// round 7
// speedup vs baseline: 1.1990x; 1.1544x over previous
#include <cuda_runtime.h>
#include <math.h>

#define NMAX 20000
#define KNN 6
#define KCAND 7
#define NPARTK 4
#define NSUB 4
#define CTOT (NPARTK*NSUB*KCAND)   /* 112 candidates per node */
#define CSLICE (CTOT/8)            /* 14 per refine thread */
#define CMERGE 48                  /* 8 slices x 6 */

typedef unsigned int u32;

// ---------------- scratch (device globals; no allocation allowed) ----------------
__device__ __align__(16) float g_cnt [NMAX];
__device__ __align__(16) float g_agg1[NMAX*16];
__device__ __align__(16) float g_x1  [NMAX*16];
__device__ __align__(16) float g_sq1 [NMAX];
__device__ __align__(16) int   g_idx1[NMAX*KNN];
__device__ __align__(16) float g_y1  [NMAX*32];
__device__ __align__(16) float g_sq2 [NMAX];
__device__ __align__(16) float g_cat0[NMAX*48];
__device__ __align__(16) float g_agg2[NMAX*48];
__device__ __align__(16) int   g_idx2[NMAX*KNN];
__device__ __align__(16) float g_x3  [NMAX*64];
__device__ __align__(16) float g_y2  [NMAX*32];
__device__ __align__(16) float g_h1  [NMAX*96];
__device__ __align__(16) float g_cd  [NMAX*CTOT];
__device__ __align__(16) int   g_ci  [NMAX*CTOT];
__device__ __align__(16) float g_md  [NMAX*CMERGE];
__device__ __align__(16) int   g_mi  [NMAX*CMERGE];

#define MMA_TF32(c0,c1,c2,c3,a0,a1,a2,a3,b0,b1) \
    asm volatile("mma.sync.aligned.m16n8k8.row.col.f32.tf32.tf32.f32 " \
        "{%0,%1,%2,%3}, {%4,%5,%6,%7}, {%8,%9}, {%0,%1,%2,%3};" \
        : "+f"(c0), "+f"(c1), "+f"(c2), "+f"(c3) \
        : "r"(a0), "r"(a1), "r"(a2), "r"(a3), "r"(b0), "r"(b1))

// ---------------- init: agg1 = x (self loop), cnt = 1 ----------------
__global__ void init1_kernel(const float* __restrict__ x, int n){
    int t = blockIdx.x*blockDim.x + threadIdx.x;
    if (t < n*16) g_agg1[t] = x[t];
    if (t < n)    g_cnt[t]  = 1.0f;
}

// ---------------- scatter-add of x[src] into agg1[dst], count edges ----------------
__global__ void scatter1_kernel(const int* __restrict__ src, const int* __restrict__ dst,
                                const float* __restrict__ x, int E){
    int t = blockIdx.x*blockDim.x + threadIdx.x;
    int e = t >> 2;
    if (e >= E) return;
    int q = t & 3;
    int s = src[e], d = dst[e];
    if (q == 0) atomicAdd(&g_cnt[d], 1.0f);
    float4 v = reinterpret_cast<const float4*>(x)[s*4 + q];
    float* a = &g_agg1[d*16 + q*4];
    atomicAdd(a+0, v.x); atomicAdd(a+1, v.y); atomicAdd(a+2, v.z); atomicAdd(a+3, v.w);
}

// ---------------- feast: out = relu((agg/cnt) @ W + b), optional ||row||^2 ----------------
template<int IN, int OUT, bool WSQ>
__global__ void feast_kernel(const float* __restrict__ agg, const float* __restrict__ W,
                             const float* __restrict__ b, int n,
                             float* __restrict__ out, float* __restrict__ sqout){
    __shared__ float sW[IN*OUT];
    __shared__ float sb[OUT];
    for (int t = threadIdx.x; t < IN*OUT; t += blockDim.x) sW[t] = W[t];
    for (int t = threadIdx.x; t < OUT;    t += blockDim.x) sb[t] = b[t];
    __syncthreads();
    int i = blockIdx.x*blockDim.x + threadIdx.x;
    if (i >= n) return;
    float inv = 1.0f / g_cnt[i];
    float acc[OUT];
#pragma unroll
    for (int c = 0; c < OUT; c++) acc[c] = sb[c];
    for (int d = 0; d < IN; d++){
        float v = agg[i*IN+d] * inv;
#pragma unroll
        for (int c = 0; c < OUT; c++) acc[c] = fmaf(v, sW[d*OUT+c], acc[c]);
    }
    float sq = 0.f;
#pragma unroll
    for (int c = 0; c < OUT; c++){
        float r = fmaxf(acc[c], 0.f);
        out[i*OUT+c] = r;
        sq = fmaf(r, r, sq);
    }
    if (WSQ) sqout[i] = sq;
}

// ---------------- streaming top-7 insertion (approx keys) ----------------
__device__ __forceinline__ void upd7(float d, int j, float bd[KCAND], int bi[KCAND]){
    if (d < bd[KCAND-1]){
        bd[KCAND-1] = d; bi[KCAND-1] = j;
#pragma unroll
        for (int k = KCAND-1; k > 0; k--){
            if (bd[k] < bd[k-1]){
                float td = bd[k]; bd[k] = bd[k-1]; bd[k-1] = td;
                int   ti = bi[k]; bi[k] = bi[k-1]; bi[k-1] = ti;
            }
        }
    }
}

// ---------------- tensor-core kNN (single tf32 pass, approx candidate keys) ----------------
// d~(i,j) = sq_j - 2 x_i.x_j via m16n8k8 tf32 (raw fp32 bits; implicit truncation).
// C initialized with sq_j so the MMA output IS the approx distance. Each warp owns
// 16 query rows; per-thread 7-deep lists over its j-residue class (g = lane&3).
// Exact fp32 refine happens in the merge kernels.
template<int DIM, int PAD>
__global__ void __launch_bounds__(256)
knn_mma_kernel(const float* __restrict__ X, const float* __restrict__ sq,
               int n, int chunk){
    const int KC = DIM/8;
    const int Q4 = DIM/4;
    __shared__ float bs[128*PAD];
    __shared__ float sqs[128];

    int tid = threadIdx.x;
    int w = tid >> 5;
    int lane = tid & 31;
    int g = lane & 3;
    int rsub = lane >> 2;
    int qbase = blockIdx.x*128 + w*16;
    int r0 = qbase + rsub;
    int r1 = r0 + 8;
    int p = blockIdx.y;
    int jbeg = p * chunk;
    int jend = min(n, jbeg + chunk);

    int rr0 = min(r0, n-1), rr1 = min(r1, n-1);
    u32 a0[KC], a1[KC], a2[KC], a3[KC];
#pragma unroll
    for (int kc = 0; kc < KC; kc++){
        a0[kc] = __float_as_uint(-2.0f * X[rr0*DIM + kc*8 + g]);
        a1[kc] = __float_as_uint(-2.0f * X[rr1*DIM + kc*8 + g]);
        a2[kc] = __float_as_uint(-2.0f * X[rr0*DIM + kc*8 + g + 4]);
        a3[kc] = __float_as_uint(-2.0f * X[rr1*DIM + kc*8 + g + 4]);
    }

    float bdA[KCAND], bdB[KCAND]; int biA[KCAND], biB[KCAND];
#pragma unroll
    for (int k = 0; k < KCAND; k++){
        bdA[k] = INFINITY; biA[k] = -1;
        bdB[k] = INFINITY; biB[k] = -1;
    }

    for (int jt = jbeg; jt < jend; jt += 128){
        __syncthreads();
        for (int idx = tid; idx < 128*Q4; idx += 256){
            int jr = idx / Q4;
            int q4 = idx % Q4;
            int gj = jt + jr;
            float4 v = {0.f,0.f,0.f,0.f};
            if (gj < jend) v = reinterpret_cast<const float4*>(X)[gj*Q4 + q4];
            int sb = jr*PAD + q4*4;
            bs[sb+0]=v.x; bs[sb+1]=v.y; bs[sb+2]=v.z; bs[sb+3]=v.w;
        }
        for (int idx = tid; idx < 128; idx += 256)
            sqs[idx] = (jt + idx < jend) ? sq[jt + idx] : INFINITY;
        __syncthreads();

#pragma unroll 2
        for (int js = 0; js < 128; js += 8){
            float2 s2 = *reinterpret_cast<const float2*>(&sqs[js + 2*g]);
            float c0 = s2.x, c1 = s2.y, c2 = s2.x, c3 = s2.y;
            int rb = (js + rsub)*PAD + g;
#pragma unroll
            for (int kc = 0; kc < KC; kc++){
                u32 b0 = __float_as_uint(bs[rb + kc*8]);
                u32 b1 = __float_as_uint(bs[rb + kc*8 + 4]);
                MMA_TF32(c0,c1,c2,c3, a0[kc],a1[kc],a2[kc],a3[kc], b0,b1);
            }
            int j0 = jt + js + 2*g;
            if (fminf(c0,c1) < bdA[KCAND-1]){
                upd7(c0, j0,   bdA, biA);
                upd7(c1, j0+1, bdA, biA);
            }
            if (fminf(c2,c3) < bdB[KCAND-1]){
                upd7(c2, j0,   bdB, biB);
                upd7(c3, j0+1, bdB, biB);
            }
        }
    }
    if (r0 < n){
        int base = r0*CTOT + (p*NSUB + g)*KCAND;
#pragma unroll
        for (int k = 0; k < KCAND; k++){ g_cd[base+k] = bdA[k]; g_ci[base+k] = biA[k]; }
    }
    if (r1 < n){
        int base = r1*CTOT + (p*NSUB + g)*KCAND;
#pragma unroll
        for (int k = 0; k < KCAND; k++){ g_cd[base+k] = bdB[k]; g_ci[base+k] = biB[k]; }
    }
}

// ---------------- refine stage A: exact fp32 recompute, 8 threads/node ----------------
// Each thread refines 14 candidates, keeps lexicographic exact top-6 locally.
template<int DIM>
__global__ void refineA_kernel(const float* __restrict__ X, const float* __restrict__ sq,
                               int n){
    const int Q4 = DIM/4;
    int t = blockIdx.x*blockDim.x + threadIdx.x;
    int i = t >> 3;
    int s = t & 7;
    if (i >= n) return;
    float4 xi[Q4];
#pragma unroll
    for (int q = 0; q < Q4; q++) xi[q] = reinterpret_cast<const float4*>(X)[i*Q4 + q];

    float bd[KNN]; unsigned bi[KNN];
#pragma unroll
    for (int k = 0; k < KNN; k++){ bd[k] = INFINITY; bi[k] = 0xFFFFFFFFu; }

    int base = i*CTOT + s*CSLICE;
    for (int c = 0; c < CSLICE; c++){
        int jraw = g_ci[base+c];
        if (jraw < 0 || jraw == i) continue;
        unsigned j = (unsigned)jraw;
        float dot = 0.f;
#pragma unroll
        for (int q = 0; q < Q4; q++){
            float4 xj = reinterpret_cast<const float4*>(X)[jraw*Q4 + q];
            dot = fmaf(xi[q].x, xj.x, dot);
            dot = fmaf(xi[q].y, xj.y, dot);
            dot = fmaf(xi[q].z, xj.z, dot);
            dot = fmaf(xi[q].w, xj.w, dot);
        }
        float e = fmaf(-2.f, dot, sq[jraw]);
        if (e < bd[KNN-1] || (e == bd[KNN-1] && j < bi[KNN-1])){
            bd[KNN-1] = e; bi[KNN-1] = j;
#pragma unroll
            for (int k = KNN-1; k > 0; k--){
                bool sw = (bd[k] < bd[k-1]) || (bd[k] == bd[k-1] && bi[k] < bi[k-1]);
                if (sw){
                    float td = bd[k]; bd[k] = bd[k-1]; bd[k-1] = td;
                    unsigned ti = bi[k]; bi[k] = bi[k-1]; bi[k-1] = ti;
                }
            }
        }
    }
    int ob = i*CMERGE + s*KNN;
#pragma unroll
    for (int k = 0; k < KNN; k++){ g_md[ob+k] = bd[k]; g_mi[ob+k] = (int)bi[k]; }
}

// ---------------- refine stage B: merge 48 exact keys -> top-6 ----------------
__global__ void refineB_kernel(int n, int* __restrict__ outidx){
    int i = blockIdx.x*blockDim.x + threadIdx.x;
    if (i >= n) return;
    float bd[KNN]; unsigned bi[KNN];
#pragma unroll
    for (int k = 0; k < KNN; k++){ bd[k] = INFINITY; bi[k] = 0xFFFFFFFFu; }
    int base = i*CMERGE;
    for (int c = 0; c < CMERGE; c++){
        float d = g_md[base+c];
        unsigned j = (unsigned)g_mi[base+c];
        if (j == 0xFFFFFFFFu) continue;
        if (d < bd[KNN-1] || (d == bd[KNN-1] && j < bi[KNN-1])){
            bd[KNN-1] = d; bi[KNN-1] = j;
#pragma unroll
            for (int k = KNN-1; k > 0; k--){
                bool sw = (bd[k] < bd[k-1]) || (bd[k] == bd[k-1] && bi[k] < bi[k-1]);
                if (sw){
                    float td = bd[k]; bd[k] = bd[k-1]; bd[k-1] = td;
                    unsigned ti = bi[k]; bi[k] = bi[k-1]; bi[k-1] = ti;
                }
            }
        }
    }
#pragma unroll
    for (int k = 0; k < KNN; k++) outidx[i*KNN+k] = (int)bi[k];
}

// ---------------- dynamic edge conv ----------------
template<int F>
__global__ void edgeconv_kernel(const float* __restrict__ X, const int* __restrict__ idx,
                                const float* __restrict__ W1, const float* __restrict__ b1,
                                const float* __restrict__ W2, const float* __restrict__ b2,
                                int n, float* __restrict__ Y, float* __restrict__ sqout){
    __shared__ float sW1[2*F*32];
    __shared__ float sb1[32];
    __shared__ float sW2[32*32];
    __shared__ float sb2[32];
    for (int t = threadIdx.x; t < 2*F*32; t += blockDim.x) sW1[t] = W1[t];
    for (int t = threadIdx.x; t < 32*32;  t += blockDim.x) sW2[t] = W2[t];
    if (threadIdx.x < 32){ sb1[threadIdx.x] = b1[threadIdx.x]; sb2[threadIdx.x] = b2[threadIdx.x]; }
    __syncthreads();
    int i = blockIdx.x*blockDim.x + threadIdx.x;
    if (i >= n) return;

    float base[32];
#pragma unroll
    for (int c = 0; c < 32; c++) base[c] = sb1[c];
    for (int d = 0; d < F; d++){
        float v = X[i*F+d];
#pragma unroll
        for (int c = 0; c < 32; c++) base[c] = fmaf(v, sW1[d*32+c], base[c]);
    }
    float acc[32];
#pragma unroll
    for (int c = 0; c < 32; c++) acc[c] = -INFINITY;

    for (int kk = 0; kk < KNN; kk++){
        int j = idx[i*KNN+kk];
        float h[32];
#pragma unroll
        for (int c = 0; c < 32; c++) h[c] = base[c];
        for (int d = 0; d < F; d++){
            float v = X[j*F+d] - X[i*F+d];
#pragma unroll
            for (int c = 0; c < 32; c++) h[c] = fmaf(v, sW1[(F+d)*32+c], h[c]);
        }
#pragma unroll
        for (int c = 0; c < 32; c++) h[c] = fmaxf(h[c], 0.f);
#pragma unroll
        for (int c = 0; c < 32; c++){
            float o = sb2[c];
#pragma unroll
            for (int k = 0; k < 32; k++) o = fmaf(h[k], sW2[k*32+c], o);
            acc[c] = fmaxf(acc[c], o);
        }
    }
    float sqv = 0.f;
#pragma unroll
    for (int c = 0; c < 32; c++){
        float r = fmaxf(acc[c], 0.f);
        Y[i*32+c] = r;
        sqv = fmaf(r, r, sqv);
    }
    if (sqout) sqout[i] = sqv;
}

// ---------------- cat0 = [x1 | y1]; agg2 init = cat0 (self loop) ----------------
__global__ void cat0_kernel(int n){
    int t = blockIdx.x*blockDim.x + threadIdx.x;
    if (t >= n*48) return;
    int i = t / 48, d = t % 48;
    float v = (d < 16) ? g_x1[i*16+d] : g_y1[i*32 + (d-16)];
    g_cat0[t] = v;
    g_agg2[t] = v;
}

__global__ void scatter2_kernel(const int* __restrict__ src, const int* __restrict__ dst, int E){
    int t = blockIdx.x*blockDim.x + threadIdx.x;
    int e = t / 12;
    if (e >= E) return;
    int q = t % 12;
    int s = src[e], d = dst[e];
    float4 v = reinterpret_cast<const float4*>(g_cat0)[s*12 + q];
    float* a = &g_agg2[d*48 + q*4];
    atomicAdd(a+0, v.x); atomicAdd(a+1, v.y); atomicAdd(a+2, v.z); atomicAdd(a+3, v.w);
}

// ---------------- MLP layer 1 ----------------
__global__ void mlp1_kernel(const float* __restrict__ W, const float* __restrict__ b, int n){
    __shared__ float sW[96*96];
    __shared__ float sb[96];
    for (int t = threadIdx.x; t < 96*96; t += blockDim.x) sW[t] = W[t];
    for (int t = threadIdx.x; t < 96;    t += blockDim.x) sb[t] = b[t];
    __syncthreads();
    int i = blockIdx.x*blockDim.x + threadIdx.x;
    if (i >= n) return;
    float acc[96];
#pragma unroll
    for (int c = 0; c < 96; c++) acc[c] = sb[c];
    for (int d = 0; d < 64; d++){
        float v = g_x3[i*64+d];
#pragma unroll
        for (int c = 0; c < 96; c++) acc[c] = fmaf(v, sW[d*96+c], acc[c]);
    }
    for (int d = 0; d < 32; d++){
        float v = g_y2[i*32+d];
#pragma unroll
        for (int c = 0; c < 96; c++) acc[c] = fmaf(v, sW[(64+d)*96+c], acc[c]);
    }
#pragma unroll
    for (int c = 0; c < 96; c++) g_h1[i*96+c] = fmaxf(acc[c], 0.f);
}

// ---------------- MLP layers 2..out ----------------
__global__ void mlp2_kernel(const float* __restrict__ W2, const float* __restrict__ b2,
                            const float* __restrict__ W3, const float* __restrict__ b3,
                            const float* __restrict__ Wo, const float* __restrict__ bo,
                            int n, float* __restrict__ out){
    __shared__ float sW2[96*32]; __shared__ float sb2v[32];
    __shared__ float sW3[32*8];  __shared__ float sb3v[8];
    __shared__ float sWo[8];     __shared__ float sbo;
    for (int t = threadIdx.x; t < 96*32; t += blockDim.x) sW2[t] = W2[t];
    for (int t = threadIdx.x; t < 32*8;  t += blockDim.x) sW3[t] = W3[t];
    if (threadIdx.x < 32) sb2v[threadIdx.x] = b2[threadIdx.x];
    if (threadIdx.x < 8){ sb3v[threadIdx.x] = b3[threadIdx.x]; sWo[threadIdx.x] = Wo[threadIdx.x]; }
    if (threadIdx.x == 0) sbo = bo[0];
    __syncthreads();
    int i = blockIdx.x*blockDim.x + threadIdx.x;
    if (i >= n) return;
    float h[32];
#pragma unroll
    for (int c = 0; c < 32; c++) h[c] = sb2v[c];
    for (int d = 0; d < 96; d++){
        float v = g_h1[i*96+d];
#pragma unroll
        for (int c = 0; c < 32; c++) h[c] = fmaf(v, sW2[d*32+c], h[c]);
    }
#pragma unroll
    for (int c = 0; c < 32; c++) h[c] = fmaxf(h[c], 0.f);
    float g[8];
#pragma unroll
    for (int c = 0; c < 8; c++){
        float o = sb3v[c];
#pragma unroll
        for (int k = 0; k < 32; k++) o = fmaf(h[k], sW3[k*8+c], o);
        g[c] = fmaxf(o, 0.f);
    }
    float z = sbo;
#pragma unroll
    for (int c = 0; c < 8; c++) z = fmaf(g[c], sWo[c], z);
    out[i] = 1.0f / (1.0f + expf(-z));
}

// ---------------- launch ----------------
extern "C" void kernel_launch(void* const* d_in, const int* in_sizes, int n_in,
                              void* d_out, int out_size){
    const float* x   = (const float*)d_in[0];
    const int*   ei  = (const int*)  d_in[1];
    int n = in_sizes[0] / 16;
    int E = in_sizes[1] / 2;
    const int* src = ei;
    const int* dst = ei + E;

    const float* cW1 = (const float*)d_in[2];
    const float* cb1 = (const float*)d_in[5];
    const float* cW3 = (const float*)d_in[6];
    const float* cb3 = (const float*)d_in[9];
    const float* e1W1=(const float*)d_in[10]; const float* e1b1=(const float*)d_in[11];
    const float* e1W2=(const float*)d_in[12]; const float* e1b2=(const float*)d_in[13];
    const float* e2W1=(const float*)d_in[14]; const float* e2b1=(const float*)d_in[15];
    const float* e2W2=(const float*)d_in[16]; const float* e2b2=(const float*)d_in[17];
    const float* l1W =(const float*)d_in[18]; const float* l1b =(const float*)d_in[19];
    const float* l2W =(const float*)d_in[20]; const float* l2b =(const float*)d_in[21];
    const float* l3W =(const float*)d_in[22]; const float* l3b =(const float*)d_in[23];
    const float* oW  =(const float*)d_in[24]; const float* ob  =(const float*)d_in[25];
    float* out = (float*)d_out;

    void *p_agg1, *p_x1, *p_sq1, *p_idx1, *p_y1, *p_sq2, *p_agg2, *p_idx2, *p_x3, *p_y2;
    cudaGetSymbolAddress(&p_agg1, g_agg1);
    cudaGetSymbolAddress(&p_x1,   g_x1);
    cudaGetSymbolAddress(&p_sq1,  g_sq1);
    cudaGetSymbolAddress(&p_idx1, g_idx1);
    cudaGetSymbolAddress(&p_y1,   g_y1);
    cudaGetSymbolAddress(&p_sq2,  g_sq2);
    cudaGetSymbolAddress(&p_agg2, g_agg2);
    cudaGetSymbolAddress(&p_idx2, g_idx2);
    cudaGetSymbolAddress(&p_x3,   g_x3);
    cudaGetSymbolAddress(&p_y2,   g_y2);

    int nb = (n + 127) / 128;
    int chunk = (n + NPARTK - 1) / NPARTK;
    dim3 knngrid(nb, NPARTK);
    int refA = (n*8 + 127) / 128;

    // FeaSt 1 (heads=1 => attention == 1 => segment-mean then GEMM)
    init1_kernel<<<(n*16 + 255)/256, 256>>>(x, n);
    scatter1_kernel<<<(E*4 + 255)/256, 256>>>(src, dst, x, E);
    feast_kernel<16,16,true><<<nb,128>>>((const float*)p_agg1, cW1, cb1, n,
                                         (float*)p_x1, (float*)p_sq1);
    // kNN on x1 (dim 16): 1-pass tf32 MMA candidates + exact fp32 refine
    knn_mma_kernel<16,20><<<knngrid,256>>>((const float*)p_x1, (const float*)p_sq1, n, chunk);
    refineA_kernel<16><<<refA,128>>>((const float*)p_x1, (const float*)p_sq1, n);
    refineB_kernel<<<(n+255)/256,256>>>(n, (int*)p_idx1);
    edgeconv_kernel<16><<<nb,128>>>((const float*)p_x1, (const int*)p_idx1,
                                    e1W1, e1b1, e1W2, e1b2, n,
                                    (float*)p_y1, (float*)p_sq2);
    // FeaSt 2 on cat0 = [x1|y1]
    cat0_kernel<<<(n*48 + 255)/256, 256>>>(n);
    scatter2_kernel<<<(E*12 + 255)/256, 256>>>(src, dst, E);
    feast_kernel<48,64,false><<<nb,128>>>((const float*)p_agg2, cW3, cb3, n,
                                          (float*)p_x3, nullptr);
    // kNN on y1 (dim 32): 1-pass tf32 MMA candidates + exact fp32 refine
    knn_mma_kernel<32,36><<<knngrid,256>>>((const float*)p_y1, (const float*)p_sq2, n, chunk);
    refineA_kernel<32><<<refA,128>>>((const float*)p_y1, (const float*)p_sq2, n);
    refineB_kernel<<<(n+255)/256,256>>>(n, (int*)p_idx2);
    edgeconv_kernel<32><<<nb,128>>>((const float*)p_y1, (const int*)p_idx2,
                                    e2W1, e2b1, e2W2, e2b2, n,
                                    (float*)p_y2, nullptr);
    // Final MLP
    mlp1_kernel<<<nb,128>>>(l1W, l1b, n);
    mlp2_kernel<<<nb,128>>>(l2W, l2b, l3W, l3b, oW, ob, n, out);
}